// round 8
// baseline (speedup 1.0000x reference)
#include <cuda_runtime.h>
#include <cuda_bf16.h>
#include <math.h>
#include <stdint.h>

// Problem constants (fixed by the reference)
#define NNODES 10000
#define NEDGES 320000
#define DIN    512
#define DHID   2048
#define NCLS   40

#define GA_ROWS 10112             // 79 * 128 (padded M; pad rows stay zero)

// GEMM1: A'[M x 1024]=[hi|lo], B'(W1^T)[2048 x 1536]=[hi|lo|hi], 24 K-chunks
#define KA1     1024
#define KB1     1536
#define BM      128
#define BN      128
#define BK      64                // 64 bf16 = 128 B per SMEM row
#define NKIT    24

// GEMM2: A2'(h')[M x 4096]=[hi|lo], B2'(W2^T)[48 x 4096]=[hi|lo]
// split-K by product term: z=0 hiA*hiB, z=1 hiA*loB, z=2 loA*hiB (32 chunks each)
#define KA2     4096
#define BM2     64
#define BN2     48                // padded from 40
#define NKIT2   32

// ---------------------------------------------------------------------------
// Device scratch (static globals: no runtime allocation allowed)
// ---------------------------------------------------------------------------
__device__ int   g_cnt[NNODES];
__device__ int   g_rowptr[NNODES + 1];
__device__ int   g_cursor[NNODES];
__device__ float g_dinv[NNODES];
__device__ int   g_csr_src[NEDGES];
__device__ float g_csr_coef[NEDGES];
__device__ __nv_bfloat16 g_Abf[(size_t)GA_ROWS * KA1];   // 20.7 MB
__device__ __nv_bfloat16 g_Bbf[(size_t)DHID * KB1];      // 6.3 MB
__device__ __nv_bfloat16 g_hbf[(size_t)GA_ROWS * KA2];   // 82.8 MB
__device__ __nv_bfloat16 g_W2bf[(size_t)BN2 * KA2];      // 393 KB
__device__ float g_t3[3][(size_t)NNODES * NCLS];         // 4.8 MB
__device__ float g_t[(size_t)NNODES * NCLS];             // 1.6 MB

// ---------------------------------------------------------------------------
// PTX helpers (baseline sm_80+ ISA: cp.async / ldmatrix / mma.sync)
// ---------------------------------------------------------------------------
__device__ __forceinline__ uint32_t smem_u32(const void* p) {
    uint32_t a;
    asm("{ .reg .u64 t; cvta.to.shared.u64 t, %1; cvt.u32.u64 %0, t; }"
        : "=r"(a) : "l"(p));
    return a;
}
__device__ __forceinline__ void cp_async16(uint32_t saddr, const void* gaddr) {
    asm volatile("cp.async.cg.shared.global [%0], [%1], 16;"
                 :: "r"(saddr), "l"(gaddr) : "memory");
}
__device__ __forceinline__ void cp_commit() {
    asm volatile("cp.async.commit_group;" ::: "memory");
}
template <int N>
__device__ __forceinline__ void cp_wait() {
    asm volatile("cp.async.wait_group %0;" :: "n"(N) : "memory");
}
__device__ __forceinline__ void ldsm_x4(uint32_t addr, uint32_t& r0, uint32_t& r1,
                                        uint32_t& r2, uint32_t& r3) {
    asm volatile("ldmatrix.sync.aligned.m8n8.x4.shared.b16 {%0,%1,%2,%3}, [%4];"
                 : "=r"(r0), "=r"(r1), "=r"(r2), "=r"(r3) : "r"(addr));
}
__device__ __forceinline__ void mma_bf16(float* d, const uint32_t* a, const uint32_t* b) {
    asm volatile(
        "mma.sync.aligned.m16n8k16.row.col.f32.bf16.bf16.f32 "
        "{%0,%1,%2,%3}, {%4,%5,%6,%7}, {%8,%9}, {%0,%1,%2,%3};"
        : "+f"(d[0]), "+f"(d[1]), "+f"(d[2]), "+f"(d[3])
        : "r"(a[0]), "r"(a[1]), "r"(a[2]), "r"(a[3]), "r"(b[0]), "r"(b[1]));
}
__device__ __forceinline__ void stcs32(void* p, uint32_t v) {
    asm volatile("st.global.cs.b32 [%0], %1;" :: "l"(p), "r"(v) : "memory");
}

union BfPair { __nv_bfloat16 h[2]; uint32_t u; };

// ---------------------------------------------------------------------------
// Init: blocks 0..47 build W2' rows; blocks 48..87 zero g_cnt
// ---------------------------------------------------------------------------
__global__ void prep_init_kernel(const float* __restrict__ W2) {
    int b = blockIdx.x;
    if (b < BN2) {
        int n = b;
        __nv_bfloat16* row = &g_W2bf[(size_t)n * KA2];
        for (int k = threadIdx.x; k < DHID; k += blockDim.x) {
            float w = (n < NCLS) ? W2[(size_t)k * NCLS + n] : 0.0f;
            __nv_bfloat16 hi = __float2bfloat16(w);
            __nv_bfloat16 lo = __float2bfloat16(w - __bfloat162float(hi));
            row[k]        = hi;
            row[2048 + k] = lo;
        }
    } else {
        int i = (b - BN2) * 256 + threadIdx.x;
        if (i < NNODES) g_cnt[i] = 0;
    }
}

__global__ void count_kernel(const int* __restrict__ dst) {
    int e = blockIdx.x * blockDim.x + threadIdx.x;
    if (e < NEDGES) atomicAdd(&g_cnt[dst[e]], 1);
}

// Single-block scan + dinv + cursor (fused)
__global__ void scan_kernel() {
    __shared__ int sh[1024];
    __shared__ int carry;
    int tid = threadIdx.x;
    if (tid == 0) { carry = 0; g_rowptr[0] = 0; }
    __syncthreads();
    for (int base = 0; base < NNODES; base += 1024) {
        int i = base + tid;
        int v = (i < NNODES) ? g_cnt[i] : 0;
        sh[tid] = v;
        __syncthreads();
        #pragma unroll
        for (int off = 1; off < 1024; off <<= 1) {
            int t = (tid >= off) ? sh[tid - off] : 0;
            __syncthreads();
            sh[tid] += t;
            __syncthreads();
        }
        int incl = sh[tid];
        if (i < NNODES) {
            g_rowptr[i + 1] = carry + incl;
            g_cursor[i]     = carry + incl - v;     // exclusive prefix
            g_dinv[i]       = rsqrtf((float)v + 1.0f);
        }
        __syncthreads();
        if (tid == 1023) carry += sh[1023];
        __syncthreads();
    }
}

__global__ void fill_kernel(const int* __restrict__ src, const int* __restrict__ dst) {
    int e = blockIdx.x * blockDim.x + threadIdx.x;
    if (e >= NEDGES) return;
    int s = src[e], d = dst[e];
    int p = atomicAdd(&g_cursor[d], 1);
    g_csr_src[p]  = s;
    g_csr_coef[p] = g_dinv[s] * g_dinv[d];
}

// ---------------------------------------------------------------------------
// W1 prep (tiled transpose): g_Bbf[n] = [hi(512) | lo(512) | hi(512)]
// ---------------------------------------------------------------------------
__global__ void w1prep_kernel(const float* __restrict__ W1) {
    __shared__ float tile[32][33];
    int k0 = blockIdx.x * 32, n0 = blockIdx.y * 32;
    int tx = threadIdx.x, ty = threadIdx.y;
    #pragma unroll
    for (int j = 0; j < 4; j++)
        tile[ty + 8 * j][tx] = W1[(size_t)(k0 + ty + 8 * j) * DHID + n0 + tx];
    __syncthreads();
    #pragma unroll
    for (int j = 0; j < 4; j++) {
        int n = n0 + ty + 8 * j;
        int k = k0 + tx;
        float w = tile[tx][ty + 8 * j];
        __nv_bfloat16 hi = __float2bfloat16(w);
        __nv_bfloat16 lo = __float2bfloat16(w - __bfloat162float(hi));
        __nv_bfloat16* row = &g_Bbf[(size_t)n * KB1];
        row[k]        = hi;
        row[512 + k]  = lo;
        row[1024 + k] = hi;
    }
}

// ---------------------------------------------------------------------------
// Layer-1 propagate + split pack: A'[i] = [hi | lo]  (edge loop unrolled x2)
// ---------------------------------------------------------------------------
__global__ void gather1_kernel(const float* __restrict__ x) {
    int i = blockIdx.x;
    int f4 = threadIdx.x;
    float di = g_dinv[i];
    float self = di * di;
    float4 xv = ((const float4*)&x[(size_t)i * DIN])[f4];
    float4 acc;
    acc.x = self * xv.x; acc.y = self * xv.y;
    acc.z = self * xv.z; acc.w = self * xv.w;
    int beg = g_rowptr[i], end = g_rowptr[i + 1];
    int j = beg;
    for (; j + 1 < end; j += 2) {
        int s0 = g_csr_src[j],     s1 = g_csr_src[j + 1];
        float c0 = g_csr_coef[j],  c1 = g_csr_coef[j + 1];
        float4 v0 = ((const float4*)&x[(size_t)s0 * DIN])[f4];
        float4 v1 = ((const float4*)&x[(size_t)s1 * DIN])[f4];
        acc.x += c0 * v0.x + c1 * v1.x;
        acc.y += c0 * v0.y + c1 * v1.y;
        acc.z += c0 * v0.z + c1 * v1.z;
        acc.w += c0 * v0.w + c1 * v1.w;
    }
    if (j < end) {
        int s = g_csr_src[j];
        float c = g_csr_coef[j];
        float4 v = ((const float4*)&x[(size_t)s * DIN])[f4];
        acc.x += c * v.x; acc.y += c * v.y;
        acc.z += c * v.z; acc.w += c * v.w;
    }
    float a[4] = {acc.x, acc.y, acc.z, acc.w};
    union { __nv_bfloat16 h[4]; uint2 u; } hp, lp;
    #pragma unroll
    for (int t = 0; t < 4; t++) {
        hp.h[t] = __float2bfloat16(a[t]);
        lp.h[t] = __float2bfloat16(a[t] - __bfloat162float(hp.h[t]));
    }
    int k = f4 * 4;
    __nv_bfloat16* row = &g_Abf[(size_t)i * KA1];
    *(uint2*)&row[k]       = hp.u;
    *(uint2*)&row[512 + k] = lp.u;
}

// ---------------------------------------------------------------------------
// GEMM1 (mma.sync bf16): h' = relu(A' @ B'^T + b1) stored split-bf16 [hi|lo]
// 128x128x64 tile, 256 threads, 3-stage cp.async pipeline, occ 2.
// One barrier per chunk: wait(kt) -> sync -> issue load(kt+2) -> compute(kt).
// ---------------------------------------------------------------------------
#define STAGE_BYTES (BM * BK * 2 + BN * BK * 2)   // 32768
#define GEMM1_SMEM  (3 * STAGE_BYTES)             // 98304

__global__ __launch_bounds__(256, 2)
void gemm1_mma_kernel(const float* __restrict__ bias) {
    extern __shared__ char dsm[];
    const uint32_t sbase = smem_u32(dsm);
    const int tid  = threadIdx.x;
    const int wid  = tid >> 5;
    const int lane = tid & 31;
    const int warp_m = wid & 3;
    const int warp_n = wid >> 2;
    const int block_n = blockIdx.x * BN;
    const int block_m = blockIdx.y * BM;

    uint32_t sA[3], sB[3];
    #pragma unroll
    for (int s = 0; s < 3; s++) {
        sA[s] = sbase + s * STAGE_BYTES;
        sB[s] = sA[s] + (uint32_t)(BM * BK * 2);
    }

    auto load_stage = [&](int kt, int s) {
        const int ka = ((kt < 8) ? kt : kt - 8) * BK;
        const int kb = kt * BK;
        #pragma unroll
        for (int i = 0; i < 4; i++) {
            int t = tid + i * 256;
            int row = t >> 3, c = t & 7;
            uint32_t sw = (uint32_t)(row << 7) + (uint32_t)(((c ^ (row & 7)) << 4));
            cp_async16(sA[s] + sw, &g_Abf[(size_t)(block_m + row) * KA1 + ka + c * 8]);
        }
        #pragma unroll
        for (int i = 0; i < 4; i++) {
            int t = tid + i * 256;
            int row = t >> 3, c = t & 7;
            uint32_t sw = (uint32_t)(row << 7) + (uint32_t)(((c ^ (row & 7)) << 4));
            cp_async16(sB[s] + sw, &g_Bbf[(size_t)(block_n + row) * KB1 + kb + c * 8]);
        }
        cp_commit();
    };

    const int grp  = lane >> 3;
    const int lrow = lane & 7;
    const int arow0 = warp_m * 32 + ((grp & 1) << 3) + lrow;
    const int arow1 = arow0 + 16;
    const int akc_half = grp >> 1;
    const int brow_base = warp_n * 64 + ((grp >> 1) << 3) + lrow;
    const int bkc_half = grp & 1;

    float acc[2][8][4];
    #pragma unroll
    for (int i = 0; i < 2; i++)
        #pragma unroll
        for (int j = 0; j < 8; j++)
            #pragma unroll
            for (int q = 0; q < 4; q++) acc[i][j][q] = 0.0f;

    load_stage(0, 0);
    load_stage(1, 1);

    for (int kt = 0; kt < NKIT; kt++) {
        const int cur = kt % 3;
        // this thread's group kt complete...
        if (kt < NKIT - 1) cp_wait<1>();
        else               cp_wait<0>();
        __syncthreads();   // ...published to all threads; buffer (kt-1)%3 freed
        if (kt + 2 < NKIT) load_stage(kt + 2, (kt + 2) % 3);

        #pragma unroll
        for (int ks = 0; ks < 4; ks++) {
            uint32_t a0[4], a1[4];
            const int kca = 2 * ks + akc_half;
            ldsm_x4(sA[cur] + (uint32_t)(arow0 << 7) + (uint32_t)(((kca ^ (arow0 & 7)) << 4)),
                    a0[0], a0[1], a0[2], a0[3]);
            ldsm_x4(sA[cur] + (uint32_t)(arow1 << 7) + (uint32_t)(((kca ^ (arow1 & 7)) << 4)),
                    a1[0], a1[1], a1[2], a1[3]);
            const int kcb = 2 * ks + bkc_half;
            uint32_t b[4][4];
            #pragma unroll
            for (int p = 0; p < 4; p++) {
                const int brow = brow_base + p * 16;
                ldsm_x4(sB[cur] + (uint32_t)(brow << 7) + (uint32_t)(((kcb ^ (brow & 7)) << 4)),
                        b[p][0], b[p][1], b[p][2], b[p][3]);
            }
            #pragma unroll
            for (int p = 0; p < 4; p++) {
                mma_bf16(acc[0][2 * p + 0], a0, &b[p][0]);
                mma_bf16(acc[0][2 * p + 1], a0, &b[p][2]);
                mma_bf16(acc[1][2 * p + 0], a1, &b[p][0]);
                mma_bf16(acc[1][2 * p + 1], a1, &b[p][2]);
            }
        }
    }

    // Epilogue: relu(acc+bias) -> split bf16 [hi | lo], streaming stores
    const int grpID = lane >> 2;
    const int tg    = lane & 3;
    #pragma unroll
    for (int mt = 0; mt < 2; mt++) {
        const int row0 = block_m + warp_m * 32 + mt * 16 + grpID;
        const int row1 = row0 + 8;
        #pragma unroll
        for (int nt = 0; nt < 8; nt++) {
            const int col = block_n + warp_n * 64 + nt * 8 + tg * 2;
            const float bi0 = bias[col], bi1 = bias[col + 1];
            {
                float v0 = fmaxf(acc[mt][nt][0] + bi0, 0.f);
                float v1 = fmaxf(acc[mt][nt][1] + bi1, 0.f);
                BfPair hp, lp;
                hp.h[0] = __float2bfloat16(v0);
                hp.h[1] = __float2bfloat16(v1);
                lp.h[0] = __float2bfloat16(v0 - __bfloat162float(hp.h[0]));
                lp.h[1] = __float2bfloat16(v1 - __bfloat162float(hp.h[1]));
                size_t base = (size_t)row0 * KA2;
                stcs32(&g_hbf[base + col],        hp.u);
                stcs32(&g_hbf[base + 2048 + col], lp.u);
            }
            {
                float v0 = fmaxf(acc[mt][nt][2] + bi0, 0.f);
                float v1 = fmaxf(acc[mt][nt][3] + bi1, 0.f);
                BfPair hp, lp;
                hp.h[0] = __float2bfloat16(v0);
                hp.h[1] = __float2bfloat16(v1);
                lp.h[0] = __float2bfloat16(v0 - __bfloat162float(hp.h[0]));
                lp.h[1] = __float2bfloat16(v1 - __bfloat162float(hp.h[1]));
                size_t base = (size_t)row1 * KA2;
                stcs32(&g_hbf[base + col],        hp.u);
                stcs32(&g_hbf[base + 2048 + col], lp.u);
            }
        }
    }
}

// ---------------------------------------------------------------------------
// GEMM2 (mma.sync bf16, split-K by term): g_t3[z] = termz(h' @ W2'^T)
// 64x48x64 tile, 128 threads, 3-stage pipeline, one barrier per chunk.
// ---------------------------------------------------------------------------
#define STAGE2_BYTES (BM2 * BK * 2 + BN2 * BK * 2)   // 14336
#define GEMM2_SMEM   (3 * STAGE2_BYTES)              // 43008

__global__ __launch_bounds__(128, 4)
void gemm2_mma_kernel() {
    extern __shared__ char dsm[];
    const uint32_t sbase = smem_u32(dsm);
    const int tid  = threadIdx.x;
    const int wid  = tid >> 5;
    const int lane = tid & 31;
    const int block_m = blockIdx.x * BM2;
    const int z = blockIdx.y;
    const int kaBase = (z == 2) ? 32 : 0;
    const int kbBase = (z == 1) ? 32 : 0;

    uint32_t sA[3], sB[3];
    #pragma unroll
    for (int s = 0; s < 3; s++) {
        sA[s] = sbase + s * STAGE2_BYTES;
        sB[s] = sA[s] + (uint32_t)(BM2 * BK * 2);
    }

    auto load_stage = [&](int kt, int s) {
        const int ka = (kaBase + kt) * BK;
        const int kb = (kbBase + kt) * BK;
        #pragma unroll
        for (int i = 0; i < 4; i++) {
            int t = tid + i * 128;
            int row = t >> 3, c = t & 7;
            uint32_t sw = (uint32_t)(row << 7) + (uint32_t)(((c ^ (row & 7)) << 4));
            cp_async16(sA[s] + sw, &g_hbf[(size_t)(block_m + row) * KA2 + ka + c * 8]);
        }
        #pragma unroll
        for (int i = 0; i < 3; i++) {
            int t = tid + i * 128;
            int row = t >> 3, c = t & 7;
            uint32_t sw = (uint32_t)(row << 7) + (uint32_t)(((c ^ (row & 7)) << 4));
            cp_async16(sB[s] + sw, &g_W2bf[(size_t)row * KA2 + kb + c * 8]);
        }
        cp_commit();
    };

    const int grp  = lane >> 3;
    const int lrow = lane & 7;
    const int arow = wid * 16 + ((grp & 1) << 3) + lrow;
    const int akc_half = grp >> 1;
    const int brow_base = ((grp >> 1) << 3) + lrow;
    const int bkc_half = grp & 1;

    float acc[6][4];
    #pragma unroll
    for (int j = 0; j < 6; j++)
        #pragma unroll
        for (int q = 0; q < 4; q++) acc[j][q] = 0.0f;

    load_stage(0, 0);
    load_stage(1, 1);

    for (int kt = 0; kt < NKIT2; kt++) {
        const int cur = kt % 3;
        if (kt < NKIT2 - 1) cp_wait<1>();
        else                cp_wait<0>();
        __syncthreads();
        if (kt + 2 < NKIT2) load_stage(kt + 2, (kt + 2) % 3);

        #pragma unroll
        for (int ks = 0; ks < 4; ks++) {
            uint32_t a[4];
            const int kca = 2 * ks + akc_half;
            ldsm_x4(sA[cur] + (uint32_t)(arow << 7) + (uint32_t)(((kca ^ (arow & 7)) << 4)),
                    a[0], a[1], a[2], a[3]);
            const int kcb = 2 * ks + bkc_half;
            uint32_t b[3][4];
            #pragma unroll
            for (int p = 0; p < 3; p++) {
                const int brow = brow_base + p * 16;
                ldsm_x4(sB[cur] + (uint32_t)(brow << 7) + (uint32_t)(((kcb ^ (brow & 7)) << 4)),
                        b[p][0], b[p][1], b[p][2], b[p][3]);
            }
            #pragma unroll
            for (int p = 0; p < 3; p++) {
                mma_bf16(acc[2 * p + 0], a, &b[p][0]);
                mma_bf16(acc[2 * p + 1], a, &b[p][2]);
            }
        }
    }

    float* dst = g_t3[z];
    const int grpID = lane >> 2;
    const int tg    = lane & 3;
    const int row0 = block_m + wid * 16 + grpID;
    const int row1 = row0 + 8;
    #pragma unroll
    for (int nt = 0; nt < 5; nt++) {
        const int col = nt * 8 + tg * 2;
        if (row0 < NNODES)
            *(float2*)&dst[(size_t)row0 * NCLS + col] = make_float2(acc[nt][0], acc[nt][1]);
        if (row1 < NNODES)
            *(float2*)&dst[(size_t)row1 * NCLS + col] = make_float2(acc[nt][2], acc[nt][3]);
    }
}

// combine the 3 split-K terms: g_t = t0 + t1 + t2
__global__ void combine_kernel() {
    int i = blockIdx.x * blockDim.x + threadIdx.x;
    const int total = NNODES * NCLS / 4;
    if (i >= total) return;
    float4 a = ((const float4*)g_t3[0])[i];
    float4 b = ((const float4*)g_t3[1])[i];
    float4 c = ((const float4*)g_t3[2])[i];
    float4 r;
    r.x = a.x + b.x + c.x;
    r.y = a.y + b.y + c.y;
    r.z = a.z + b.z + c.z;
    r.w = a.w + b.w + c.w;
    ((float4*)g_t)[i] = r;
}

// ---------------------------------------------------------------------------
// Layer-2 propagate + bias
// ---------------------------------------------------------------------------
__global__ void gather2_kernel(const float* __restrict__ b2, float* __restrict__ out) {
    int gw = (blockIdx.x * blockDim.x + threadIdx.x) >> 5;
    int lane = threadIdx.x & 31;
    if (gw >= NNODES) return;
    int i = gw;
    float di = g_dinv[i];
    float self = di * di;
    int c1 = lane + 32;
    float acc0 = 0.f, acc1 = 0.f;
    int beg = g_rowptr[i], end = g_rowptr[i + 1];
    for (int j = beg; j < end; j++) {
        int s = g_csr_src[j];
        float c = g_csr_coef[j];
        acc0 += c * g_t[(size_t)s * NCLS + lane];
        if (lane < 8) acc1 += c * g_t[(size_t)s * NCLS + c1];
    }
    out[(size_t)i * NCLS + lane] = acc0 + self * g_t[(size_t)i * NCLS + lane] + b2[lane];
    if (lane < 8)
        out[(size_t)i * NCLS + c1] = acc1 + self * g_t[(size_t)i * NCLS + c1] + b2[c1];
}

// ---------------------------------------------------------------------------
// Entry point
// ---------------------------------------------------------------------------
extern "C" void kernel_launch(void* const* d_in, const int* in_sizes, int n_in,
                              void* d_out, int out_size) {
    const float* x   = (const float*)d_in[0];
    const int*   ei  = (const int*)d_in[1];
    const float* W1  = (const float*)d_in[2];
    const float* b1  = (const float*)d_in[3];
    const float* W2  = (const float*)d_in[4];
    const float* b2  = (const float*)d_in[5];
    float*       out = (float*)d_out;

    const int* src = ei;
    const int* dst = ei + NEDGES;

    cudaFuncSetAttribute(gemm1_mma_kernel,
                         cudaFuncAttributeMaxDynamicSharedMemorySize, GEMM1_SMEM);
    cudaFuncSetAttribute(gemm2_mma_kernel,
                         cudaFuncAttributeMaxDynamicSharedMemorySize, GEMM2_SMEM);

    // Init (W2 prep + zero counters), CSR build
    prep_init_kernel<<<BN2 + (NNODES + 255) / 256, 256>>>(W2);
    count_kernel<<<(NEDGES + 255) / 256, 256>>>(dst);
    scan_kernel<<<1, 1024>>>();
    fill_kernel<<<(NEDGES + 255) / 256, 256>>>(src, dst);

    // W1 prep
    {
        dim3 grid(DIN / 32, DHID / 32), block(32, 8);
        w1prep_kernel<<<grid, block>>>(W1);
    }

    // Layer 1
    gather1_kernel<<<NNODES, 128>>>(x);
    {
        dim3 grid(DHID / BN, GA_ROWS / BM);   // (16, 79)
        gemm1_mma_kernel<<<grid, 256, GEMM1_SMEM>>>(b1);
    }

    // Layer 2 (split-K gemm + combine + propagate)
    {
        dim3 grid(GA_ROWS / BM2, 3);          // (158, 3)
        gemm2_mma_kernel<<<grid, 128, GEMM2_SMEM>>>();
    }
    combine_kernel<<<(NNODES * NCLS / 4 + 255) / 256, 256>>>();
    gather2_kernel<<<(NNODES * 32 + 127) / 128, 128>>>(b2, out);
}

// round 9
// speedup vs baseline: 1.0446x; 1.0446x over previous
#include <cuda_runtime.h>
#include <cuda_bf16.h>
#include <math.h>
#include <stdint.h>

// Problem constants (fixed by the reference)
#define NNODES 10000
#define NEDGES 320000
#define DIN    512
#define DHID   2048
#define NCLS   40

#define GA_ROWS 10112             // 79 * 128 (padded M; pad rows stay zero)

// GEMM1: A'[M x 1024]=[hi|lo], B'(W1^T)[2048 x 1536]=[hi|lo|hi], 24 K-chunks
#define KA1     1024
#define KB1     1536
#define BM      128
#define BN      128
#define BK      64                // 64 bf16 = 128 B per SMEM row
#define NKIT    24

// GEMM2: split-K by product term over h'[M x 4096]=[hi|lo], W2'[48 x 4096]
#define KA2     4096
#define BM2     64
#define BN2     48
#define NKIT2   32

// ---------------------------------------------------------------------------
// Device scratch (static globals: no runtime allocation allowed)
// ---------------------------------------------------------------------------
__device__ int   g_cnt[NNODES];
__device__ int   g_rowptr[NNODES + 1];
__device__ int   g_cursor[NNODES];
__device__ float g_dinv[NNODES];
__device__ int   g_csr_src[NEDGES];
__device__ float g_csr_coef[NEDGES];
__device__ __nv_bfloat16 g_Abf[(size_t)GA_ROWS * KA1];   // 20.7 MB
__device__ __nv_bfloat16 g_Bbf[(size_t)DHID * KB1];      // 6.3 MB
__device__ __nv_bfloat16 g_hbf[(size_t)GA_ROWS * KA2];   // 82.8 MB
__device__ __nv_bfloat16 g_W2bf[(size_t)BN2 * KA2];      // 393 KB
__device__ float g_t3[3][(size_t)NNODES * NCLS];         // 4.8 MB
__device__ float g_t[(size_t)NNODES * NCLS];             // 1.6 MB

// ---------------------------------------------------------------------------
// PTX helpers
// ---------------------------------------------------------------------------
__device__ __forceinline__ uint32_t smem_u32(const void* p) {
    uint32_t a;
    asm("{ .reg .u64 t; cvta.to.shared.u64 t, %1; cvt.u32.u64 %0, t; }"
        : "=r"(a) : "l"(p));
    return a;
}
__device__ __forceinline__ void cp_async16(uint32_t saddr, const void* gaddr) {
    asm volatile("cp.async.cg.shared.global [%0], [%1], 16;"
                 :: "r"(saddr), "l"(gaddr) : "memory");
}
__device__ __forceinline__ void cp_commit() {
    asm volatile("cp.async.commit_group;" ::: "memory");
}
template <int N>
__device__ __forceinline__ void cp_wait() {
    asm volatile("cp.async.wait_group %0;" :: "n"(N) : "memory");
}
__device__ __forceinline__ void ldsm_x4(uint32_t addr, uint32_t& r0, uint32_t& r1,
                                        uint32_t& r2, uint32_t& r3) {
    asm volatile("ldmatrix.sync.aligned.m8n8.x4.shared.b16 {%0,%1,%2,%3}, [%4];"
                 : "=r"(r0), "=r"(r1), "=r"(r2), "=r"(r3) : "r"(addr));
}
__device__ __forceinline__ void mma_bf16(float* d, const uint32_t* a, const uint32_t* b) {
    asm volatile(
        "mma.sync.aligned.m16n8k16.row.col.f32.bf16.bf16.f32 "
        "{%0,%1,%2,%3}, {%4,%5,%6,%7}, {%8,%9}, {%0,%1,%2,%3};"
        : "+f"(d[0]), "+f"(d[1]), "+f"(d[2]), "+f"(d[3])
        : "r"(a[0]), "r"(a[1]), "r"(a[2]), "r"(a[3]), "r"(b[0]), "r"(b[1]));
}
__device__ __forceinline__ void stcs32(void* p, uint32_t v) {
    asm volatile("st.global.cs.b32 [%0], %1;" :: "l"(p), "r"(v) : "memory");
}

union BfPair { __nv_bfloat16 h[2]; uint32_t u; };

// ---------------------------------------------------------------------------
// Init: blocks 0..47 build W2' rows; blocks 48..87 zero g_cnt
// ---------------------------------------------------------------------------
__global__ void prep_init_kernel(const float* __restrict__ W2) {
    int b = blockIdx.x;
    if (b < BN2) {
        int n = b;
        __nv_bfloat16* row = &g_W2bf[(size_t)n * KA2];
        for (int k = threadIdx.x; k < DHID; k += blockDim.x) {
            float w = (n < NCLS) ? W2[(size_t)k * NCLS + n] : 0.0f;
            __nv_bfloat16 hi = __float2bfloat16(w);
            __nv_bfloat16 lo = __float2bfloat16(w - __bfloat162float(hi));
            row[k]        = hi;
            row[2048 + k] = lo;
        }
    } else {
        int i = (b - BN2) * 256 + threadIdx.x;
        if (i < NNODES) g_cnt[i] = 0;
    }
}

__global__ void count_kernel(const int* __restrict__ dst) {
    int e = blockIdx.x * blockDim.x + threadIdx.x;
    if (e < NEDGES) atomicAdd(&g_cnt[dst[e]], 1);
}

// Single-block warp-shuffle scan + dinv + cursor (4 barriers per tile)
__global__ void scan_kernel() {
    __shared__ int warp_sums[32];
    __shared__ int s_carry;
    int tid = threadIdx.x, lane = tid & 31, w = tid >> 5;
    if (tid == 0) { s_carry = 0; g_rowptr[0] = 0; }
    __syncthreads();
    for (int base = 0; base < NNODES; base += 1024) {
        int i = base + tid;
        int v = (i < NNODES) ? g_cnt[i] : 0;
        int x = v;
        #pragma unroll
        for (int off = 1; off < 32; off <<= 1) {
            int t = __shfl_up_sync(0xFFFFFFFFu, x, off);
            if (lane >= off) x += t;
        }
        if (lane == 31) warp_sums[w] = x;
        __syncthreads();
        if (w == 0) {
            int s = warp_sums[lane];
            #pragma unroll
            for (int off = 1; off < 32; off <<= 1) {
                int t = __shfl_up_sync(0xFFFFFFFFu, s, off);
                if (lane >= off) s += t;
            }
            warp_sums[lane] = s;
        }
        __syncthreads();
        int warp_off = (w > 0) ? warp_sums[w - 1] : 0;
        int incl = x + warp_off + s_carry;
        if (i < NNODES) {
            g_rowptr[i + 1] = incl;
            g_cursor[i]     = incl - v;
            g_dinv[i]       = rsqrtf((float)v + 1.0f);
        }
        __syncthreads();
        if (tid == 0) s_carry += warp_sums[31];
        __syncthreads();
    }
}

__global__ void fill_kernel(const int* __restrict__ src, const int* __restrict__ dst) {
    int e = blockIdx.x * blockDim.x + threadIdx.x;
    if (e >= NEDGES) return;
    int s = src[e], d = dst[e];
    int p = atomicAdd(&g_cursor[d], 1);
    g_csr_src[p]  = s;
    g_csr_coef[p] = g_dinv[s] * g_dinv[d];
}

// ---------------------------------------------------------------------------
// W1 prep (tiled transpose): g_Bbf[n] = [hi(512) | lo(512) | hi(512)]
// ---------------------------------------------------------------------------
__global__ void w1prep_kernel(const float* __restrict__ W1) {
    __shared__ float tile[32][33];
    int k0 = blockIdx.x * 32, n0 = blockIdx.y * 32;
    int tx = threadIdx.x, ty = threadIdx.y;
    #pragma unroll
    for (int j = 0; j < 4; j++)
        tile[ty + 8 * j][tx] = W1[(size_t)(k0 + ty + 8 * j) * DHID + n0 + tx];
    __syncthreads();
    #pragma unroll
    for (int j = 0; j < 4; j++) {
        int n = n0 + ty + 8 * j;
        int k = k0 + tx;
        float w = tile[tx][ty + 8 * j];
        __nv_bfloat16 hi = __float2bfloat16(w);
        __nv_bfloat16 lo = __float2bfloat16(w - __bfloat162float(hi));
        __nv_bfloat16* row = &g_Bbf[(size_t)n * KB1];
        row[k]        = hi;
        row[512 + k]  = lo;
        row[1024 + k] = hi;
    }
}

// ---------------------------------------------------------------------------
// Layer-1 propagate + split pack: A'[i] = [hi | lo]
// ---------------------------------------------------------------------------
__global__ void gather1_kernel(const float* __restrict__ x) {
    int i = blockIdx.x;
    int f4 = threadIdx.x;
    float di = g_dinv[i];
    float self = di * di;
    float4 xv = ((const float4*)&x[(size_t)i * DIN])[f4];
    float4 acc;
    acc.x = self * xv.x; acc.y = self * xv.y;
    acc.z = self * xv.z; acc.w = self * xv.w;
    int beg = g_rowptr[i], end = g_rowptr[i + 1];
    int j = beg;
    for (; j + 1 < end; j += 2) {
        int s0 = g_csr_src[j],     s1 = g_csr_src[j + 1];
        float c0 = g_csr_coef[j],  c1 = g_csr_coef[j + 1];
        float4 v0 = ((const float4*)&x[(size_t)s0 * DIN])[f4];
        float4 v1 = ((const float4*)&x[(size_t)s1 * DIN])[f4];
        acc.x += c0 * v0.x + c1 * v1.x;
        acc.y += c0 * v0.y + c1 * v1.y;
        acc.z += c0 * v0.z + c1 * v1.z;
        acc.w += c0 * v0.w + c1 * v1.w;
    }
    if (j < end) {
        int s = g_csr_src[j];
        float c = g_csr_coef[j];
        float4 v = ((const float4*)&x[(size_t)s * DIN])[f4];
        acc.x += c * v.x; acc.y += c * v.y;
        acc.z += c * v.z; acc.w += c * v.w;
    }
    float a[4] = {acc.x, acc.y, acc.z, acc.w};
    union { __nv_bfloat16 h[4]; uint2 u; } hp, lp;
    #pragma unroll
    for (int t = 0; t < 4; t++) {
        hp.h[t] = __float2bfloat16(a[t]);
        lp.h[t] = __float2bfloat16(a[t] - __bfloat162float(hp.h[t]));
    }
    int k = f4 * 4;
    __nv_bfloat16* row = &g_Abf[(size_t)i * KA1];
    *(uint2*)&row[k]       = hp.u;
    *(uint2*)&row[512 + k] = lp.u;
}

// ---------------------------------------------------------------------------
// GEMM1 (mma.sync bf16): h' = relu(A' @ B'^T + b1) stored split-bf16 [hi|lo]
// 128x128x64 CTA tile, 128 threads (4 warps, 2x2, warp tile 64x64).
// 3-stage cp.async pipeline, occ 2. One barrier per chunk:
//   wait(kt) -> sync -> issue load(kt+2) -> compute(kt)
// Warp tile 64x64 cuts LDSM smem traffic 33% vs 8-warp 32x64.
// ---------------------------------------------------------------------------
#define STAGE_BYTES (BM * BK * 2 + BN * BK * 2)   // 32768
#define GEMM1_SMEM  (3 * STAGE_BYTES)             // 98304

__global__ __launch_bounds__(128, 2)
void gemm1_mma_kernel(const float* __restrict__ bias) {
    extern __shared__ char dsm[];
    const uint32_t sbase = smem_u32(dsm);
    const int tid  = threadIdx.x;
    const int wid  = tid >> 5;
    const int lane = tid & 31;
    const int warp_m = wid & 1;       // 2 warps over M=128 (64 each)
    const int warp_n = wid >> 1;      // 2 warps over N=128 (64 each)
    const int block_n = blockIdx.x * BN;
    const int block_m = blockIdx.y * BM;

    uint32_t sA[3], sB[3];
    #pragma unroll
    for (int s = 0; s < 3; s++) {
        sA[s] = sbase + s * STAGE_BYTES;
        sB[s] = sA[s] + (uint32_t)(BM * BK * 2);
    }

    auto load_stage = [&](int kt, int s) {
        const int ka = ((kt < 8) ? kt : kt - 8) * BK;
        const int kb = kt * BK;
        #pragma unroll
        for (int i = 0; i < 8; i++) {                 // A: 1024 chunks / 128 thr
            int t = tid + i * 128;
            int row = t >> 3, c = t & 7;
            uint32_t sw = (uint32_t)(row << 7) + (uint32_t)(((c ^ (row & 7)) << 4));
            cp_async16(sA[s] + sw, &g_Abf[(size_t)(block_m + row) * KA1 + ka + c * 8]);
        }
        #pragma unroll
        for (int i = 0; i < 8; i++) {                 // B: 1024 chunks
            int t = tid + i * 128;
            int row = t >> 3, c = t & 7;
            uint32_t sw = (uint32_t)(row << 7) + (uint32_t)(((c ^ (row & 7)) << 4));
            cp_async16(sB[s] + sw, &g_Bbf[(size_t)(block_n + row) * KB1 + kb + c * 8]);
        }
        cp_commit();
    };

    const int grp  = lane >> 3;
    const int lrow = lane & 7;
    // A row base per mt (mt*16), kc-half from grp>>1
    const int arow_base = warp_m * 64 + ((grp & 1) << 3) + lrow;
    const int akc_half = grp >> 1;
    // B row base per nt-pair (p*16), kc-half from grp&1
    const int brow_base = warp_n * 64 + ((grp >> 1) << 3) + lrow;
    const int bkc_half = grp & 1;

    float acc[4][8][4];
    #pragma unroll
    for (int i = 0; i < 4; i++)
        #pragma unroll
        for (int j = 0; j < 8; j++)
            #pragma unroll
            for (int q = 0; q < 4; q++) acc[i][j][q] = 0.0f;

    load_stage(0, 0);
    load_stage(1, 1);

    for (int kt = 0; kt < NKIT; kt++) {
        const int cur = kt % 3;
        if (kt < NKIT - 1) cp_wait<1>();
        else               cp_wait<0>();
        __syncthreads();
        if (kt + 2 < NKIT) load_stage(kt + 2, (kt + 2) % 3);

        #pragma unroll
        for (int ks = 0; ks < 4; ks++) {
            uint32_t a[4][4];
            const int kca = 2 * ks + akc_half;
            #pragma unroll
            for (int mt = 0; mt < 4; mt++) {
                const int arow = arow_base + mt * 16;
                ldsm_x4(sA[cur] + (uint32_t)(arow << 7) + (uint32_t)(((kca ^ (arow & 7)) << 4)),
                        a[mt][0], a[mt][1], a[mt][2], a[mt][3]);
            }
            const int kcb = 2 * ks + bkc_half;
            uint32_t b[4][4];
            #pragma unroll
            for (int p = 0; p < 4; p++) {
                const int brow = brow_base + p * 16;
                ldsm_x4(sB[cur] + (uint32_t)(brow << 7) + (uint32_t)(((kcb ^ (brow & 7)) << 4)),
                        b[p][0], b[p][1], b[p][2], b[p][3]);
            }
            #pragma unroll
            for (int mt = 0; mt < 4; mt++)
                #pragma unroll
                for (int p = 0; p < 4; p++) {
                    mma_bf16(acc[mt][2 * p + 0], a[mt], &b[p][0]);
                    mma_bf16(acc[mt][2 * p + 1], a[mt], &b[p][2]);
                }
        }
    }

    // Epilogue: relu(acc+bias) -> split bf16 [hi | lo], streaming stores
    const int grpID = lane >> 2;
    const int tg    = lane & 3;
    #pragma unroll
    for (int mt = 0; mt < 4; mt++) {
        const int row0 = block_m + warp_m * 64 + mt * 16 + grpID;
        const int row1 = row0 + 8;
        #pragma unroll
        for (int nt = 0; nt < 8; nt++) {
            const int col = block_n + warp_n * 64 + nt * 8 + tg * 2;
            const float bi0 = bias[col], bi1 = bias[col + 1];
            {
                float v0 = fmaxf(acc[mt][nt][0] + bi0, 0.f);
                float v1 = fmaxf(acc[mt][nt][1] + bi1, 0.f);
                BfPair hp, lp;
                hp.h[0] = __float2bfloat16(v0);
                hp.h[1] = __float2bfloat16(v1);
                lp.h[0] = __float2bfloat16(v0 - __bfloat162float(hp.h[0]));
                lp.h[1] = __float2bfloat16(v1 - __bfloat162float(hp.h[1]));
                size_t base = (size_t)row0 * KA2;
                stcs32(&g_hbf[base + col],        hp.u);
                stcs32(&g_hbf[base + 2048 + col], lp.u);
            }
            {
                float v0 = fmaxf(acc[mt][nt][2] + bi0, 0.f);
                float v1 = fmaxf(acc[mt][nt][3] + bi1, 0.f);
                BfPair hp, lp;
                hp.h[0] = __float2bfloat16(v0);
                hp.h[1] = __float2bfloat16(v1);
                lp.h[0] = __float2bfloat16(v0 - __bfloat162float(hp.h[0]));
                lp.h[1] = __float2bfloat16(v1 - __bfloat162float(hp.h[1]));
                size_t base = (size_t)row1 * KA2;
                stcs32(&g_hbf[base + col],        hp.u);
                stcs32(&g_hbf[base + 2048 + col], lp.u);
            }
        }
    }
}

// ---------------------------------------------------------------------------
// GEMM2 (mma.sync bf16, split-K by term): g_t3[z] = termz(h' @ W2'^T)
// 64x48x64 tile, 128 threads, 3-stage pipeline, one barrier per chunk.
// ---------------------------------------------------------------------------
#define STAGE2_BYTES (BM2 * BK * 2 + BN2 * BK * 2)   // 14336
#define GEMM2_SMEM   (3 * STAGE2_BYTES)              // 43008

__global__ __launch_bounds__(128, 4)
void gemm2_mma_kernel() {
    extern __shared__ char dsm[];
    const uint32_t sbase = smem_u32(dsm);
    const int tid  = threadIdx.x;
    const int wid  = tid >> 5;
    const int lane = tid & 31;
    const int block_m = blockIdx.x * BM2;
    const int z = blockIdx.y;
    const int kaBase = (z == 2) ? 32 : 0;
    const int kbBase = (z == 1) ? 32 : 0;

    uint32_t sA[3], sB[3];
    #pragma unroll
    for (int s = 0; s < 3; s++) {
        sA[s] = sbase + s * STAGE2_BYTES;
        sB[s] = sA[s] + (uint32_t)(BM2 * BK * 2);
    }

    auto load_stage = [&](int kt, int s) {
        const int ka = (kaBase + kt) * BK;
        const int kb = (kbBase + kt) * BK;
        #pragma unroll
        for (int i = 0; i < 4; i++) {
            int t = tid + i * 128;
            int row = t >> 3, c = t & 7;
            uint32_t sw = (uint32_t)(row << 7) + (uint32_t)(((c ^ (row & 7)) << 4));
            cp_async16(sA[s] + sw, &g_hbf[(size_t)(block_m + row) * KA2 + ka + c * 8]);
        }
        #pragma unroll
        for (int i = 0; i < 3; i++) {
            int t = tid + i * 128;
            int row = t >> 3, c = t & 7;
            uint32_t sw = (uint32_t)(row << 7) + (uint32_t)(((c ^ (row & 7)) << 4));
            cp_async16(sB[s] + sw, &g_W2bf[(size_t)row * KA2 + kb + c * 8]);
        }
        cp_commit();
    };

    const int grp  = lane >> 3;
    const int lrow = lane & 7;
    const int arow = wid * 16 + ((grp & 1) << 3) + lrow;
    const int akc_half = grp >> 1;
    const int brow_base = ((grp >> 1) << 3) + lrow;
    const int bkc_half = grp & 1;

    float acc[6][4];
    #pragma unroll
    for (int j = 0; j < 6; j++)
        #pragma unroll
        for (int q = 0; q < 4; q++) acc[j][q] = 0.0f;

    load_stage(0, 0);
    load_stage(1, 1);

    for (int kt = 0; kt < NKIT2; kt++) {
        const int cur = kt % 3;
        if (kt < NKIT2 - 1) cp_wait<1>();
        else                cp_wait<0>();
        __syncthreads();
        if (kt + 2 < NKIT2) load_stage(kt + 2, (kt + 2) % 3);

        #pragma unroll
        for (int ks = 0; ks < 4; ks++) {
            uint32_t a[4];
            const int kca = 2 * ks + akc_half;
            ldsm_x4(sA[cur] + (uint32_t)(arow << 7) + (uint32_t)(((kca ^ (arow & 7)) << 4)),
                    a[0], a[1], a[2], a[3]);
            const int kcb = 2 * ks + bkc_half;
            uint32_t b[3][4];
            #pragma unroll
            for (int p = 0; p < 3; p++) {
                const int brow = brow_base + p * 16;
                ldsm_x4(sB[cur] + (uint32_t)(brow << 7) + (uint32_t)(((kcb ^ (brow & 7)) << 4)),
                        b[p][0], b[p][1], b[p][2], b[p][3]);
            }
            #pragma unroll
            for (int p = 0; p < 3; p++) {
                mma_bf16(acc[2 * p + 0], a, &b[p][0]);
                mma_bf16(acc[2 * p + 1], a, &b[p][2]);
            }
        }
    }

    float* dst = g_t3[z];
    const int grpID = lane >> 2;
    const int tg    = lane & 3;
    const int row0 = block_m + wid * 16 + grpID;
    const int row1 = row0 + 8;
    #pragma unroll
    for (int nt = 0; nt < 5; nt++) {
        const int col = nt * 8 + tg * 2;
        if (row0 < NNODES)
            *(float2*)&dst[(size_t)row0 * NCLS + col] = make_float2(acc[nt][0], acc[nt][1]);
        if (row1 < NNODES)
            *(float2*)&dst[(size_t)row1 * NCLS + col] = make_float2(acc[nt][2], acc[nt][3]);
    }
}

// combine the 3 split-K terms: g_t = t0 + t1 + t2
__global__ void combine_kernel() {
    int i = blockIdx.x * blockDim.x + threadIdx.x;
    const int total = NNODES * NCLS / 4;
    if (i >= total) return;
    float4 a = ((const float4*)g_t3[0])[i];
    float4 b = ((const float4*)g_t3[1])[i];
    float4 c = ((const float4*)g_t3[2])[i];
    float4 r;
    r.x = a.x + b.x + c.x;
    r.y = a.y + b.y + c.y;
    r.z = a.z + b.z + c.z;
    r.w = a.w + b.w + c.w;
    ((float4*)g_t)[i] = r;
}

// ---------------------------------------------------------------------------
// Layer-2 propagate + bias
// ---------------------------------------------------------------------------
__global__ void gather2_kernel(const float* __restrict__ b2, float* __restrict__ out) {
    int gw = (blockIdx.x * blockDim.x + threadIdx.x) >> 5;
    int lane = threadIdx.x & 31;
    if (gw >= NNODES) return;
    int i = gw;
    float di = g_dinv[i];
    float self = di * di;
    int c1 = lane + 32;
    float acc0 = 0.f, acc1 = 0.f;
    int beg = g_rowptr[i], end = g_rowptr[i + 1];
    for (int j = beg; j < end; j++) {
        int s = g_csr_src[j];
        float c = g_csr_coef[j];
        acc0 += c * g_t[(size_t)s * NCLS + lane];
        if (lane < 8) acc1 += c * g_t[(size_t)s * NCLS + c1];
    }
    out[(size_t)i * NCLS + lane] = acc0 + self * g_t[(size_t)i * NCLS + lane] + b2[lane];
    if (lane < 8)
        out[(size_t)i * NCLS + c1] = acc1 + self * g_t[(size_t)i * NCLS + c1] + b2[c1];
}

// ---------------------------------------------------------------------------
// Entry point
// ---------------------------------------------------------------------------
extern "C" void kernel_launch(void* const* d_in, const int* in_sizes, int n_in,
                              void* d_out, int out_size) {
    const float* x   = (const float*)d_in[0];
    const int*   ei  = (const int*)d_in[1];
    const float* W1  = (const float*)d_in[2];
    const float* b1  = (const float*)d_in[3];
    const float* W2  = (const float*)d_in[4];
    const float* b2  = (const float*)d_in[5];
    float*       out = (float*)d_out;

    const int* src = ei;
    const int* dst = ei + NEDGES;

    cudaFuncSetAttribute(gemm1_mma_kernel,
                         cudaFuncAttributeMaxDynamicSharedMemorySize, GEMM1_SMEM);
    cudaFuncSetAttribute(gemm2_mma_kernel,
                         cudaFuncAttributeMaxDynamicSharedMemorySize, GEMM2_SMEM);

    // Init (W2 prep + zero counters), CSR build
    prep_init_kernel<<<BN2 + (NNODES + 255) / 256, 256>>>(W2);
    count_kernel<<<(NEDGES + 255) / 256, 256>>>(dst);
    scan_kernel<<<1, 1024>>>();
    fill_kernel<<<(NEDGES + 255) / 256, 256>>>(src, dst);

    // W1 prep
    {
        dim3 grid(DIN / 32, DHID / 32), block(32, 8);
        w1prep_kernel<<<grid, block>>>(W1);
    }

    // Layer 1
    gather1_kernel<<<NNODES, 128>>>(x);
    {
        dim3 grid(DHID / BN, GA_ROWS / BM);   // (16, 79)
        gemm1_mma_kernel<<<grid, 128, GEMM1_SMEM>>>(b1);
    }

    // Layer 2 (split-K gemm + combine + propagate)
    {
        dim3 grid(GA_ROWS / BM2, 3);          // (158, 3)
        gemm2_mma_kernel<<<grid, 128, GEMM2_SMEM>>>();
    }
    combine_kernel<<<(NNODES * NCLS / 4 + 255) / 256, 256>>>();
    gather2_kernel<<<(NNODES * 32 + 127) / 128, 128>>>(b2, out);
}

// round 10
// speedup vs baseline: 1.1398x; 1.0911x over previous
#include <cuda_runtime.h>
#include <cuda_bf16.h>
#include <math.h>
#include <stdint.h>

// Problem constants (fixed by the reference)
#define NNODES 10000
#define NEDGES 320000
#define DIN    512
#define DHID   2048
#define NCLS   40

#define GA_ROWS 10112             // 79 * 128 (padded M; pad rows stay zero)

// GEMM1: A'[M x 1024]=[hi|lo], B'(W1^T)[2048 x 1536]=[hi|lo|hi], 24 K-chunks
#define KA1     1024
#define KB1     1536
#define BM      128
#define BN      128
#define BK      64                // 64 bf16 = 128 B per SMEM row
#define NKIT    24

#define KA2     4096              // W2' row width: [hi(2048) | lo(2048)]
#define NCP     48                // padded class count

// ---------------------------------------------------------------------------
// Device scratch (static globals: no runtime allocation allowed)
// ---------------------------------------------------------------------------
__device__ int   g_cnt[NNODES];
__device__ int   g_rowptr[NNODES + 1];
__device__ int   g_cursor[NNODES];
__device__ float g_dinv[NNODES];
__device__ int   g_csr_src[NEDGES];
__device__ float g_csr_coef[NEDGES];
__device__ __nv_bfloat16 g_Abf[(size_t)GA_ROWS * KA1];   // 20.7 MB
__device__ __nv_bfloat16 g_Bbf[(size_t)DHID * KB1];      // 6.3 MB
__device__ __nv_bfloat16 g_W2bf[(size_t)NCP * KA2];      // 393 KB
__device__ float g_tp[32][(size_t)NNODES * NCP];         // 61.4 MB partials
__device__ float g_t[(size_t)NNODES * NCLS];             // 1.6 MB

// ---------------------------------------------------------------------------
// PTX helpers
// ---------------------------------------------------------------------------
__device__ __forceinline__ uint32_t smem_u32(const void* p) {
    uint32_t a;
    asm("{ .reg .u64 t; cvta.to.shared.u64 t, %1; cvt.u32.u64 %0, t; }"
        : "=r"(a) : "l"(p));
    return a;
}
__device__ __forceinline__ void cp_async16(uint32_t saddr, const void* gaddr) {
    asm volatile("cp.async.cg.shared.global [%0], [%1], 16;"
                 :: "r"(saddr), "l"(gaddr) : "memory");
}
__device__ __forceinline__ void cp_commit() {
    asm volatile("cp.async.commit_group;" ::: "memory");
}
template <int N>
__device__ __forceinline__ void cp_wait() {
    asm volatile("cp.async.wait_group %0;" :: "n"(N) : "memory");
}
__device__ __forceinline__ void ldsm_x4(uint32_t addr, uint32_t& r0, uint32_t& r1,
                                        uint32_t& r2, uint32_t& r3) {
    asm volatile("ldmatrix.sync.aligned.m8n8.x4.shared.b16 {%0,%1,%2,%3}, [%4];"
                 : "=r"(r0), "=r"(r1), "=r"(r2), "=r"(r3) : "r"(addr));
}
__device__ __forceinline__ void mma_bf16(float* d, const uint32_t* a, const uint32_t* b) {
    asm volatile(
        "mma.sync.aligned.m16n8k16.row.col.f32.bf16.bf16.f32 "
        "{%0,%1,%2,%3}, {%4,%5,%6,%7}, {%8,%9}, {%0,%1,%2,%3};"
        : "+f"(d[0]), "+f"(d[1]), "+f"(d[2]), "+f"(d[3])
        : "r"(a[0]), "r"(a[1]), "r"(a[2]), "r"(a[3]), "r"(b[0]), "r"(b[1]));
}
__device__ __forceinline__ void stcs_f2(void* p, float a, float b) {
    asm volatile("st.global.cs.v2.f32 [%0], {%1, %2};"
                 :: "l"(p), "f"(a), "f"(b) : "memory");
}
// pack two fp32 -> bf16x2 (v0 in low half), and produce the lo-residual pack
__device__ __forceinline__ uint32_t pack_split(float v0, float v1, uint32_t& loOut) {
    uint32_t hi;
    asm("cvt.rn.bf16x2.f32 %0, %1, %2;" : "=r"(hi) : "f"(v1), "f"(v0));
    float h0 = __uint_as_float(hi << 16);
    float h1 = __uint_as_float(hi & 0xffff0000u);
    float l0 = v0 - h0, l1 = v1 - h1;
    asm("cvt.rn.bf16x2.f32 %0, %1, %2;" : "=r"(loOut) : "f"(l1), "f"(l0));
    return hi;
}

// ---------------------------------------------------------------------------
// Init: blocks 0..47 build W2' rows; blocks 48..87 zero g_cnt
// ---------------------------------------------------------------------------
__global__ void prep_init_kernel(const float* __restrict__ W2) {
    int b = blockIdx.x;
    if (b < NCP) {
        int n = b;
        __nv_bfloat16* row = &g_W2bf[(size_t)n * KA2];
        for (int k = threadIdx.x; k < DHID; k += blockDim.x) {
            float w = (n < NCLS) ? W2[(size_t)k * NCLS + n] : 0.0f;
            __nv_bfloat16 hi = __float2bfloat16(w);
            __nv_bfloat16 lo = __float2bfloat16(w - __bfloat162float(hi));
            row[k]        = hi;
            row[2048 + k] = lo;
        }
    } else {
        int i = (b - NCP) * 256 + threadIdx.x;
        if (i < NNODES) g_cnt[i] = 0;
    }
}

__global__ void count_kernel(const int* __restrict__ dst) {
    int e = blockIdx.x * blockDim.x + threadIdx.x;
    if (e < NEDGES) atomicAdd(&g_cnt[dst[e]], 1);
}

// Single-block warp-shuffle scan + dinv + cursor
__global__ void scan_kernel() {
    __shared__ int warp_sums[32];
    __shared__ int s_carry;
    int tid = threadIdx.x, lane = tid & 31, w = tid >> 5;
    if (tid == 0) { s_carry = 0; g_rowptr[0] = 0; }
    __syncthreads();
    for (int base = 0; base < NNODES; base += 1024) {
        int i = base + tid;
        int v = (i < NNODES) ? g_cnt[i] : 0;
        int x = v;
        #pragma unroll
        for (int off = 1; off < 32; off <<= 1) {
            int t = __shfl_up_sync(0xFFFFFFFFu, x, off);
            if (lane >= off) x += t;
        }
        if (lane == 31) warp_sums[w] = x;
        __syncthreads();
        if (w == 0) {
            int s = warp_sums[lane];
            #pragma unroll
            for (int off = 1; off < 32; off <<= 1) {
                int t = __shfl_up_sync(0xFFFFFFFFu, s, off);
                if (lane >= off) s += t;
            }
            warp_sums[lane] = s;
        }
        __syncthreads();
        int warp_off = (w > 0) ? warp_sums[w - 1] : 0;
        int incl = x + warp_off + s_carry;
        if (i < NNODES) {
            g_rowptr[i + 1] = incl;
            g_cursor[i]     = incl - v;
            g_dinv[i]       = rsqrtf((float)v + 1.0f);
        }
        __syncthreads();
        if (tid == 0) s_carry += warp_sums[31];
        __syncthreads();
    }
}

__global__ void fill_kernel(const int* __restrict__ src, const int* __restrict__ dst) {
    int e = blockIdx.x * blockDim.x + threadIdx.x;
    if (e >= NEDGES) return;
    int s = src[e], d = dst[e];
    int p = atomicAdd(&g_cursor[d], 1);
    g_csr_src[p]  = s;
    g_csr_coef[p] = g_dinv[s] * g_dinv[d];
}

// ---------------------------------------------------------------------------
// W1 prep (tiled transpose): g_Bbf[n] = [hi(512) | lo(512) | hi(512)]
// ---------------------------------------------------------------------------
__global__ void w1prep_kernel(const float* __restrict__ W1) {
    __shared__ float tile[32][33];
    int k0 = blockIdx.x * 32, n0 = blockIdx.y * 32;
    int tx = threadIdx.x, ty = threadIdx.y;
    #pragma unroll
    for (int j = 0; j < 4; j++)
        tile[ty + 8 * j][tx] = W1[(size_t)(k0 + ty + 8 * j) * DHID + n0 + tx];
    __syncthreads();
    #pragma unroll
    for (int j = 0; j < 4; j++) {
        int n = n0 + ty + 8 * j;
        int k = k0 + tx;
        float w = tile[tx][ty + 8 * j];
        __nv_bfloat16 hi = __float2bfloat16(w);
        __nv_bfloat16 lo = __float2bfloat16(w - __bfloat162float(hi));
        __nv_bfloat16* row = &g_Bbf[(size_t)n * KB1];
        row[k]        = hi;
        row[512 + k]  = lo;
        row[1024 + k] = hi;
    }
}

// ---------------------------------------------------------------------------
// Layer-1 propagate + split pack: A'[i] = [hi | lo]
// ---------------------------------------------------------------------------
__global__ void gather1_kernel(const float* __restrict__ x) {
    int i = blockIdx.x;
    int f4 = threadIdx.x;
    float di = g_dinv[i];
    float self = di * di;
    float4 xv = ((const float4*)&x[(size_t)i * DIN])[f4];
    float4 acc;
    acc.x = self * xv.x; acc.y = self * xv.y;
    acc.z = self * xv.z; acc.w = self * xv.w;
    int beg = g_rowptr[i], end = g_rowptr[i + 1];
    int j = beg;
    for (; j + 1 < end; j += 2) {
        int s0 = g_csr_src[j],     s1 = g_csr_src[j + 1];
        float c0 = g_csr_coef[j],  c1 = g_csr_coef[j + 1];
        float4 v0 = ((const float4*)&x[(size_t)s0 * DIN])[f4];
        float4 v1 = ((const float4*)&x[(size_t)s1 * DIN])[f4];
        acc.x += c0 * v0.x + c1 * v1.x;
        acc.y += c0 * v0.y + c1 * v1.y;
        acc.z += c0 * v0.z + c1 * v1.z;
        acc.w += c0 * v0.w + c1 * v1.w;
    }
    if (j < end) {
        int s = g_csr_src[j];
        float c = g_csr_coef[j];
        float4 v = ((const float4*)&x[(size_t)s * DIN])[f4];
        acc.x += c * v.x; acc.y += c * v.y;
        acc.z += c * v.z; acc.w += c * v.w;
    }
    float a[4] = {acc.x, acc.y, acc.z, acc.w};
    union { __nv_bfloat16 h[4]; uint2 u; } hp, lp;
    #pragma unroll
    for (int t = 0; t < 4; t++) {
        hp.h[t] = __float2bfloat16(a[t]);
        lp.h[t] = __float2bfloat16(a[t] - __bfloat162float(hp.h[t]));
    }
    int k = f4 * 4;
    __nv_bfloat16* row = &g_Abf[(size_t)i * KA1];
    *(uint2*)&row[k]       = hp.u;
    *(uint2*)&row[512 + k] = lp.u;
}

// ---------------------------------------------------------------------------
// Fused GEMM1+GEMM2 (mma.sync bf16):
//   h_block = relu(A' @ B'^T + b1)   (fp32 in registers, never materialized)
//   partial[c] = h_block @ W2_slice  (3-term split, A-frags built from C-frags)
// 128x128x64 CTA tile, 128 threads (4 warps, 2x2, warp tile 64x64), 3-stage
// pipeline, occ 2. Each warp writes a [64 x 48] fp32 partial into slice
// (blockIdx.x*2 + warp_n); combine_kernel sums the 32 slices.
// ---------------------------------------------------------------------------
#define STAGE_BYTES (BM * BK * 2 + BN * BK * 2)   // 32768
#define GEMM1_SMEM  (3 * STAGE_BYTES)             // 98304

__global__ __launch_bounds__(128, 2)
void gemm_fused_kernel(const float* __restrict__ bias) {
    extern __shared__ char dsm[];
    const uint32_t sbase = smem_u32(dsm);
    const int tid  = threadIdx.x;
    const int wid  = tid >> 5;
    const int lane = tid & 31;
    const int warp_m = wid & 1;
    const int warp_n = wid >> 1;
    const int block_n = blockIdx.x * BN;
    const int block_m = blockIdx.y * BM;

    uint32_t sA[3], sB[3];
    #pragma unroll
    for (int s = 0; s < 3; s++) {
        sA[s] = sbase + s * STAGE_BYTES;
        sB[s] = sA[s] + (uint32_t)(BM * BK * 2);
    }

    auto load_stage = [&](int kt, int s) {
        const int ka = ((kt < 8) ? kt : kt - 8) * BK;
        const int kb = kt * BK;
        #pragma unroll
        for (int i = 0; i < 8; i++) {
            int t = tid + i * 128;
            int row = t >> 3, c = t & 7;
            uint32_t sw = (uint32_t)(row << 7) + (uint32_t)(((c ^ (row & 7)) << 4));
            cp_async16(sA[s] + sw, &g_Abf[(size_t)(block_m + row) * KA1 + ka + c * 8]);
        }
        #pragma unroll
        for (int i = 0; i < 8; i++) {
            int t = tid + i * 128;
            int row = t >> 3, c = t & 7;
            uint32_t sw = (uint32_t)(row << 7) + (uint32_t)(((c ^ (row & 7)) << 4));
            cp_async16(sB[s] + sw, &g_Bbf[(size_t)(block_n + row) * KB1 + kb + c * 8]);
        }
        cp_commit();
    };

    const int grp  = lane >> 3;
    const int lrow = lane & 7;
    const int arow_base = warp_m * 64 + ((grp & 1) << 3) + lrow;
    const int akc_half = grp >> 1;
    const int brow_base = warp_n * 64 + ((grp >> 1) << 3) + lrow;
    const int bkc_half = grp & 1;

    float acc[4][8][4];
    #pragma unroll
    for (int i = 0; i < 4; i++)
        #pragma unroll
        for (int j = 0; j < 8; j++)
            #pragma unroll
            for (int q = 0; q < 4; q++) acc[i][j][q] = 0.0f;

    load_stage(0, 0);
    load_stage(1, 1);

    for (int kt = 0; kt < NKIT; kt++) {
        const int cur = kt % 3;
        if (kt < NKIT - 1) cp_wait<1>();
        else               cp_wait<0>();
        __syncthreads();
        if (kt + 2 < NKIT) load_stage(kt + 2, (kt + 2) % 3);

        #pragma unroll
        for (int ks = 0; ks < 4; ks++) {
            uint32_t a[4][4];
            const int kca = 2 * ks + akc_half;
            #pragma unroll
            for (int mt = 0; mt < 4; mt++) {
                const int arow = arow_base + mt * 16;
                ldsm_x4(sA[cur] + (uint32_t)(arow << 7) + (uint32_t)(((kca ^ (arow & 7)) << 4)),
                        a[mt][0], a[mt][1], a[mt][2], a[mt][3]);
            }
            const int kcb = 2 * ks + bkc_half;
            uint32_t b[4][4];
            #pragma unroll
            for (int p = 0; p < 4; p++) {
                const int brow = brow_base + p * 16;
                ldsm_x4(sB[cur] + (uint32_t)(brow << 7) + (uint32_t)(((kcb ^ (brow & 7)) << 4)),
                        b[p][0], b[p][1], b[p][2], b[p][3]);
            }
            #pragma unroll
            for (int mt = 0; mt < 4; mt++)
                #pragma unroll
                for (int p = 0; p < 4; p++) {
                    mma_bf16(acc[mt][2 * p + 0], a[mt], &b[p][0]);
                    mma_bf16(acc[mt][2 * p + 1], a[mt], &b[p][2]);
                }
        }
    }

    // ------- Fused epilogue: partial = relu(acc+b1) @ W2_slice -------
    // Load W2 slice [48 x 128] hi + lo into stage-0 smem (24 KB), 256-B rows,
    // 16-chunk swizzle: sw = (c&8) | ((c ^ (row&7)) & 7).
    __syncthreads();   // everyone done with pipeline smem
    const uint32_t sW = sbase;
    #pragma unroll
    for (int i = 0; i < 12; i++) {
        int t = tid + i * 128;                 // 0..1535
        int blk = (t >= 768) ? 1 : 0;
        int q = t - blk * 768;
        int row = q >> 4, c = q & 15;
        uint32_t sw = (uint32_t)((c & 8) | ((c ^ (row & 7)) & 7));
        cp_async16(sW + (uint32_t)(blk * 12288 + row * 256) + (sw << 4),
                   &g_W2bf[(size_t)row * KA2 + blk * 2048 + block_n + c * 8]);
    }
    cp_commit();
    cp_wait<0>();
    __syncthreads();

    const int grpID = lane >> 2;
    const int tg    = lane & 3;
    const int brow_lane = ((grp >> 1) << 3) + lrow;   // 0..15
    float* dst = g_tp[blockIdx.x * 2 + warp_n];

    #pragma unroll
    for (int mt = 0; mt < 4; mt++) {
        float t2[6][4];
        #pragma unroll
        for (int t = 0; t < 6; t++)
            #pragma unroll
            for (int q = 0; q < 4; q++) t2[t][q] = 0.0f;

        #pragma unroll
        for (int j = 0; j < 4; j++) {
            // bias + relu + split for cols [16j, 16j+16) of this warp's n range
            int colA = block_n + warp_n * 64 + 16 * j + tg * 2;
            float b00 = bias[colA],     b01 = bias[colA + 1];
            float b10 = bias[colA + 8], b11 = bias[colA + 9];
            float v00 = fmaxf(acc[mt][2 * j][0] + b00, 0.f);
            float v01 = fmaxf(acc[mt][2 * j][1] + b01, 0.f);
            float v02 = fmaxf(acc[mt][2 * j][2] + b00, 0.f);
            float v03 = fmaxf(acc[mt][2 * j][3] + b01, 0.f);
            float v10 = fmaxf(acc[mt][2 * j + 1][0] + b10, 0.f);
            float v11 = fmaxf(acc[mt][2 * j + 1][1] + b11, 0.f);
            float v12 = fmaxf(acc[mt][2 * j + 1][2] + b10, 0.f);
            float v13 = fmaxf(acc[mt][2 * j + 1][3] + b11, 0.f);

            uint32_t aHi[4], aLo[4];
            aHi[0] = pack_split(v00, v01, aLo[0]);
            aHi[1] = pack_split(v02, v03, aLo[1]);
            aHi[2] = pack_split(v10, v11, aLo[2]);
            aHi[3] = pack_split(v12, v13, aLo[3]);

            const int cfull = warp_n * 8 + 2 * j + bkc_half;   // 16B-chunk 0..15
            uint32_t bHi[3][4], bLo[3][4];
            #pragma unroll
            for (int p = 0; p < 3; p++) {
                const int brow = brow_lane + p * 16;
                uint32_t sw = (uint32_t)((cfull & 8) | ((cfull ^ (brow & 7)) & 7));
                uint32_t off = (uint32_t)(brow * 256) + (sw << 4);
                ldsm_x4(sW + off,         bHi[p][0], bHi[p][1], bHi[p][2], bHi[p][3]);
                ldsm_x4(sW + 12288 + off, bLo[p][0], bLo[p][1], bLo[p][2], bLo[p][3]);
            }
            #pragma unroll
            for (int p = 0; p < 3; p++) {
                mma_bf16(t2[2 * p + 0], aHi, &bHi[p][0]);
                mma_bf16(t2[2 * p + 1], aHi, &bHi[p][2]);
                mma_bf16(t2[2 * p + 0], aHi, &bLo[p][0]);
                mma_bf16(t2[2 * p + 1], aHi, &bLo[p][2]);
                mma_bf16(t2[2 * p + 0], aLo, &bHi[p][0]);
                mma_bf16(t2[2 * p + 1], aLo, &bHi[p][2]);
            }
        }

        const int r0 = block_m + warp_m * 64 + mt * 16 + grpID;
        const int r1 = r0 + 8;
        #pragma unroll
        for (int t = 0; t < 6; t++) {
            const int col = t * 8 + tg * 2;
            if (r0 < NNODES) stcs_f2(&dst[(size_t)r0 * NCP + col], t2[t][0], t2[t][1]);
            if (r1 < NNODES) stcs_f2(&dst[(size_t)r1 * NCP + col], t2[t][2], t2[t][3]);
        }
    }
}

// combine the 32 partial slices: g_t[r, 0..39] = sum_z g_tp[z][r, 0..39]
__global__ void combine_kernel() {
    int idx = blockIdx.x * blockDim.x + threadIdx.x;   // over NNODES * 10
    if (idx >= NNODES * 10) return;
    int r = idx / 10, q = idx % 10;
    float4 s = make_float4(0.f, 0.f, 0.f, 0.f);
    #pragma unroll
    for (int z = 0; z < 32; z++) {
        float4 v = *(const float4*)&g_tp[z][(size_t)r * NCP + q * 4];
        s.x += v.x; s.y += v.y; s.z += v.z; s.w += v.w;
    }
    *(float4*)&g_t[(size_t)r * NCLS + q * 4] = s;
}

// ---------------------------------------------------------------------------
// Layer-2 propagate + bias
// ---------------------------------------------------------------------------
__global__ void gather2_kernel(const float* __restrict__ b2, float* __restrict__ out) {
    int gw = (blockIdx.x * blockDim.x + threadIdx.x) >> 5;
    int lane = threadIdx.x & 31;
    if (gw >= NNODES) return;
    int i = gw;
    float di = g_dinv[i];
    float self = di * di;
    int c1 = lane + 32;
    float acc0 = 0.f, acc1 = 0.f;
    int beg = g_rowptr[i], end = g_rowptr[i + 1];
    for (int j = beg; j < end; j++) {
        int s = g_csr_src[j];
        float c = g_csr_coef[j];
        acc0 += c * g_t[(size_t)s * NCLS + lane];
        if (lane < 8) acc1 += c * g_t[(size_t)s * NCLS + c1];
    }
    out[(size_t)i * NCLS + lane] = acc0 + self * g_t[(size_t)i * NCLS + lane] + b2[lane];
    if (lane < 8)
        out[(size_t)i * NCLS + c1] = acc1 + self * g_t[(size_t)i * NCLS + c1] + b2[c1];
}

// ---------------------------------------------------------------------------
// Entry point
// ---------------------------------------------------------------------------
extern "C" void kernel_launch(void* const* d_in, const int* in_sizes, int n_in,
                              void* d_out, int out_size) {
    const float* x   = (const float*)d_in[0];
    const int*   ei  = (const int*)d_in[1];
    const float* W1  = (const float*)d_in[2];
    const float* b1  = (const float*)d_in[3];
    const float* W2  = (const float*)d_in[4];
    const float* b2  = (const float*)d_in[5];
    float*       out = (float*)d_out;

    const int* src = ei;
    const int* dst = ei + NEDGES;

    cudaFuncSetAttribute(gemm_fused_kernel,
                         cudaFuncAttributeMaxDynamicSharedMemorySize, GEMM1_SMEM);

    // Init (W2' prep + zero counters), CSR build
    prep_init_kernel<<<NCP + (NNODES + 255) / 256, 256>>>(W2);
    count_kernel<<<(NEDGES + 255) / 256, 256>>>(dst);
    scan_kernel<<<1, 1024>>>();
    fill_kernel<<<(NEDGES + 255) / 256, 256>>>(src, dst);

    // W1 prep
    {
        dim3 grid(DIN / 32, DHID / 32), block(32, 8);
        w1prep_kernel<<<grid, block>>>(W1);
    }

    // Layer 1 + fused layer-2 GEMM
    gather1_kernel<<<NNODES, 128>>>(x);
    {
        dim3 grid(DHID / BN, GA_ROWS / BM);   // (16, 79)
        gemm_fused_kernel<<<grid, 128, GEMM1_SMEM>>>(b1);
    }

    // Combine partials, then layer-2 propagate
    combine_kernel<<<(NNODES * 10 + 255) / 256, 256>>>();
    gather2_kernel<<<(NNODES * 32 + 127) / 128, 128>>>(b2, out);
}